// round 9
// baseline (speedup 1.0000x reference)
#include <cuda_runtime.h>
#include <cstdint>

#define N_NODES 100000
#define N_EDGES 3200000
#define F_IN    1433
#define F_HID   16
#define F_OUT   7

#define KPAD     1536            // F_IN padded to multiple of 128 (zero-filled W)
#define G1_GRID  296             // 148 SMs x 2 blocks
#define NCHUNK   (N_NODES / 4)   // 25000 4-row warp chunks

// ---------------- scratch (device globals; no allocation allowed) ----------
__device__ float g_h1  [N_NODES * F_HID];   // ns-scaled X @ W1
__device__ float g_agg1[N_NODES * F_HID];   // gather-aggregated layer 1
__device__ float g_h2  [N_NODES * 8];       // padded to 8
__device__ float g_degout[N_NODES];
__device__ int   g_degin [N_NODES];         // int in-degree (CSR)
__device__ float g_ns[N_NODES];
__device__ float g_nd[N_NODES];
__device__ int   g_off   [N_NODES];         // CSR range start per dst
__device__ int   g_cursor[N_NODES];         // initialized to g_off
__device__ int   g_csr_src[N_EDGES];
__device__ int   g_total;

// ---- packed f32x2 helpers (sm_103a FFMA2 — PTX-only form) ------------------
__device__ __forceinline__ unsigned long long fma2(unsigned long long a,
                                                   unsigned long long b,
                                                   unsigned long long c) {
    unsigned long long d;
    asm("fma.rn.f32x2 %0, %1, %2, %3;" : "=l"(d) : "l"(a), "l"(b), "l"(c));
    return d;
}
__device__ __forceinline__ unsigned long long add2(unsigned long long a,
                                                   unsigned long long b) {
    unsigned long long d;
    asm("add.rn.f32x2 %0, %1, %2;" : "=l"(d) : "l"(a), "l"(b));
    return d;
}
__device__ __forceinline__ unsigned long long splat2(float x) {
    unsigned long long d;
    asm("mov.b64 %0, {%1, %1};" : "=l"(d) : "f"(x));
    return d;
}
__device__ __forceinline__ float2 unpack2(unsigned long long v) {
    float2 r;
    asm("mov.b64 {%0, %1}, %2;" : "=f"(r.x), "=f"(r.y) : "l"(v));
    return r;
}
__device__ __forceinline__ float ldcs(const float* p) {
    float v;
    asm("ld.global.cs.f32 %0, [%1];" : "=f"(v) : "l"(p));
    return v;
}

// ---------------- zeroing (graph-replay safe) --------------------------------
__global__ void zero_kernel() {
    int t = blockIdx.x * blockDim.x + threadIdx.x;
    if (t < N_NODES) { g_degout[t] = 0.f; g_degin[t] = 0; }
    if (t == 0) g_total = 0;
}

// ---------------- degrees (4 edges/thread, 8 independent REDs) ---------------
__global__ void degree_kernel(const int* __restrict__ src,
                              const int* __restrict__ dst) {
    int base = (blockIdx.x * blockDim.x + threadIdx.x) * 4;
    if (base >= N_EDGES) return;
    int4 s4 = *(const int4*)(src + base);
    int4 d4 = *(const int4*)(dst + base);
    atomicAdd(&g_degout[s4.x], 1.0f);
    atomicAdd(&g_degout[s4.y], 1.0f);
    atomicAdd(&g_degout[s4.z], 1.0f);
    atomicAdd(&g_degout[s4.w], 1.0f);
    atomicAdd(&g_degin[d4.x], 1);
    atomicAdd(&g_degin[d4.y], 1);
    atomicAdd(&g_degin[d4.z], 1);
    atomicAdd(&g_degin[d4.w], 1);
}

// ---------------- norms + CSR offsets (warp-aggregated range assignment) ----
__global__ void norm_offset_kernel() {
    int n = blockIdx.x * blockDim.x + threadIdx.x;
    if (n >= N_NODES) return;
    int lane = threadIdx.x & 31;
    int d = g_degin[n];

    int incl = d;
#pragma unroll
    for (int o = 1; o < 32; o <<= 1) {
        int v = __shfl_up_sync(0xffffffffu, incl, o);
        if (lane >= o) incl += v;
    }
    int base = 0;
    if (lane == 31) base = atomicAdd(&g_total, incl);
    base = __shfl_sync(0xffffffffu, base, 31);

    int off = base + incl - d;
    g_off[n]    = off;
    g_cursor[n] = off;
    g_ns[n] = rsqrtf(fmaxf(g_degout[n], 1.0f));
    g_nd[n] = rsqrtf(fmaxf((float)d, 1.0f));
}

// ---------------- CSR edge placement (4 edges/thread, 4 atomics in flight) ---
__global__ void place_kernel(const int* __restrict__ src,
                             const int* __restrict__ dst) {
    int base = (blockIdx.x * blockDim.x + threadIdx.x) * 4;
    if (base >= N_EDGES) return;
    int4 d4 = *(const int4*)(dst + base);
    int4 s4 = *(const int4*)(src + base);
    int p0 = atomicAdd(&g_cursor[d4.x], 1);
    int p1 = atomicAdd(&g_cursor[d4.y], 1);
    int p2 = atomicAdd(&g_cursor[d4.z], 1);
    int p3 = atomicAdd(&g_cursor[d4.w], 1);
    g_csr_src[p0] = s4.x;
    g_csr_src[p1] = s4.y;
    g_csr_src[p2] = s4.z;
    g_csr_src[p3] = s4.w;
}

// ---------------- GEMM1: h1 = diag(ns) * X @ W1  (unchanged) ----------------
__global__ __launch_bounds__(256, 2) void gemm1_kernel(const float* __restrict__ X,
                                                       const float* __restrict__ W) {
    extern __shared__ unsigned long long sWp[];   // [8][KPAD] packed float2

    const float2* Wv = (const float2*)W;          // Wv[k*8 + p]
    for (int idx = threadIdx.x; idx < 8 * KPAD; idx += 256) {
        int k = idx >> 3, p = idx & 7;
        float2 v = (k < F_IN) ? Wv[k * 8 + p] : make_float2(0.f, 0.f);
        unsigned long long pk;
        asm("mov.b64 %0, {%1, %2};" : "=l"(pk) : "f"(v.x), "f"(v.y));
        sWp[p * KPAD + k] = pk;
    }
    __syncthreads();

    const int lane = threadIdx.x & 31;
    const int gw   = blockIdx.x * 8 + (threadIdx.x >> 5);

    for (int chunk = gw; chunk < NCHUNK; chunk += G1_GRID * 8) {
        const unsigned m0   = (unsigned)chunk * 4u;
        const unsigned base = m0 * (unsigned)F_IN;

        unsigned long long acc[32];
#pragma unroll
        for (int a = 0; a < 32; a++) acc[a] = 0ull;

        float Axa[4], Axb[4];
        float Bxa[4], Bxb[4];
        float Cxa[4], Cxb[4];

#define COMPUTE_BLOCK(k0v, xa, xb)                                            \
        {                                                                     \
            const int kA = (k0v) + lane;                                      \
            unsigned long long xx[4];                                         \
            _Pragma("unroll")                                                 \
            for (int i = 0; i < 4; i++) xx[i] = splat2(xa[i]);                \
            _Pragma("unroll")                                                 \
            for (int p = 0; p < 8; p++) {                                     \
                unsigned long long w = sWp[p * KPAD + kA];                    \
                _Pragma("unroll")                                             \
                for (int i = 0; i < 4; i++)                                   \
                    acc[i * 8 + p] = fma2(xx[i], w, acc[i * 8 + p]);          \
            }                                                                 \
            const int kB = (k0v) + 32 + lane;                                 \
            _Pragma("unroll")                                                 \
            for (int i = 0; i < 4; i++) xx[i] = splat2(xb[i]);                \
            _Pragma("unroll")                                                 \
            for (int p = 0; p < 8; p++) {                                     \
                unsigned long long w = sWp[p * KPAD + kB];                    \
                _Pragma("unroll")                                             \
                for (int i = 0; i < 4; i++)                                   \
                    acc[i * 8 + p] = fma2(xx[i], w, acc[i * 8 + p]);          \
            }                                                                 \
        }

#define PREFETCH_BLOCK(k0v, xa, xb)                                           \
        {                                                                     \
            const unsigned ka = (unsigned)min((k0v) + lane,      F_IN - 1);   \
            const unsigned kb = (unsigned)min((k0v) + 32 + lane, F_IN - 1);   \
            _Pragma("unroll")                                                 \
            for (int i = 0; i < 4; i++) {                                     \
                xa[i] = ldcs(X + base + (unsigned)i * F_IN + ka);             \
                xb[i] = ldcs(X + base + (unsigned)i * F_IN + kb);             \
            }                                                                 \
        }

        PREFETCH_BLOCK(0,  Axa, Axb);
        PREFETCH_BLOCK(64, Bxa, Bxb);

#pragma unroll 1
        for (int t = 0; t < 8; t++) {
            const int kb0 = t * 192;
            PREFETCH_BLOCK(kb0 + 128, Cxa, Cxb);
            COMPUTE_BLOCK (kb0,       Axa, Axb);
            PREFETCH_BLOCK(kb0 + 192, Axa, Axb);
            COMPUTE_BLOCK (kb0 + 64,  Bxa, Bxb);
            PREFETCH_BLOCK(kb0 + 256, Bxa, Bxb);
            COMPUTE_BLOCK (kb0 + 128, Cxa, Cxb);
        }
#undef COMPUTE_BLOCK
#undef PREFETCH_BLOCK

        // transpose-reduce: lane l ends with acc slot (row = l>>3, pcol = l&7)
        {
            int n = 32;
#pragma unroll
            for (int m = 16; m > 0; m >>= 1) {
                n >>= 1;
#pragma unroll
                for (int j = 0; j < 16; j++) {
                    if (j >= n) break;
                    unsigned long long mine = (lane & m) ? acc[j]     : acc[j + n];
                    unsigned long long keep = (lane & m) ? acc[j + n] : acc[j];
                    unsigned long long recv = __shfl_xor_sync(0xffffffffu, mine, m);
                    acc[j] = add2(keep, recv);
                }
            }
        }
        {
            const int i = lane >> 3, p = lane & 7;
            float s = g_ns[m0 + i];
            float2 v = unpack2(acc[0]);
            float2* o = (float2*)(g_h1 + (size_t)(m0 + i) * F_HID);
            o[p] = make_float2(v.x * s, v.y * s);
        }
    }
}

// ---------------- agg1: agg1[n] = sum_{e in CSR[n]} h1[src(e)]  (16 wide) ---
__global__ __launch_bounds__(256) void agg1_kernel() {
    int gw   = blockIdx.x * 8 + (threadIdx.x >> 5);   // node id (grid exact)
    int lane = threadIdx.x & 31;
    int q  = lane & 3;
    int es = lane >> 2;

    int o  = g_off[gw];
    int nE = g_degin[gw];

    float4 acc = make_float4(0.f, 0.f, 0.f, 0.f);
    const float4* h1v = (const float4*)g_h1;
    for (int i = es; i < nE; i += 8) {
        int s = __ldg(&g_csr_src[o + i]);
        float4 v = h1v[(size_t)s * 4 + q];
        acc.x += v.x; acc.y += v.y; acc.z += v.z; acc.w += v.w;
    }
#pragma unroll
    for (int m = 4; m <= 16; m <<= 1) {
        acc.x += __shfl_xor_sync(0xffffffffu, acc.x, m);
        acc.y += __shfl_xor_sync(0xffffffffu, acc.y, m);
        acc.z += __shfl_xor_sync(0xffffffffu, acc.z, m);
        acc.w += __shfl_xor_sync(0xffffffffu, acc.w, m);
    }
    if (lane < 4) ((float4*)g_agg1)[(size_t)gw * 4 + lane] = acc;
}

// ---------------- GEMM2: h2 = diag(ns) * relu(agg1*nd + b1) @ W2 ------------
__global__ void gemm2_kernel(const float* __restrict__ b1,
                             const float* __restrict__ W2) {
    __shared__ float sW[F_HID * F_OUT];
    __shared__ float sb[F_HID];
    if (threadIdx.x < F_HID * F_OUT) sW[threadIdx.x] = W2[threadIdx.x];
    if (threadIdx.x < F_HID)         sb[threadIdx.x] = b1[threadIdx.x];
    __syncthreads();

    int n = blockIdx.x * blockDim.x + threadIdx.x;
    if (n >= N_NODES) return;

    float ndv = g_nd[n], nsv = g_ns[n];
    const float4* a4 = (const float4*)(g_agg1 + (size_t)n * F_HID);
    float x[F_HID];
#pragma unroll
    for (int q = 0; q < 4; q++) {
        float4 v = a4[q];
        x[q*4+0] = v.x; x[q*4+1] = v.y; x[q*4+2] = v.z; x[q*4+3] = v.w;
    }
    float o[F_OUT];
#pragma unroll
    for (int j = 0; j < F_OUT; j++) o[j] = 0.f;
#pragma unroll
    for (int i = 0; i < F_HID; i++) {
        float xi = fmaxf(fmaf(x[i], ndv, sb[i]), 0.f) * nsv;
#pragma unroll
        for (int j = 0; j < F_OUT; j++) o[j] = fmaf(xi, sW[i * F_OUT + j], o[j]);
    }
    float4* hp = (float4*)(g_h2 + (size_t)n * 8);
    hp[0] = make_float4(o[0], o[1], o[2], o[3]);
    hp[1] = make_float4(o[4], o[5], o[6], 0.f);   // pad lane stays 0
}

// ---------------- agg2 + finalize: out[n] = (sum h2[src]) * nd + b2 ----------
__global__ __launch_bounds__(256) void agg2_final_kernel(const float* __restrict__ b2,
                                                         float* __restrict__ out) {
    int gw   = blockIdx.x * 8 + (threadIdx.x >> 5);
    int lane = threadIdx.x & 31;
    int q  = lane & 1;
    int es = lane >> 1;

    int o  = g_off[gw];
    int nE = g_degin[gw];

    float4 acc = make_float4(0.f, 0.f, 0.f, 0.f);
    const float4* h2v = (const float4*)g_h2;
    for (int i = es; i < nE; i += 16) {
        int s = __ldg(&g_csr_src[o + i]);
        float4 v = h2v[(size_t)s * 2 + q];
        acc.x += v.x; acc.y += v.y; acc.z += v.z; acc.w += v.w;
    }
#pragma unroll
    for (int m = 2; m <= 16; m <<= 1) {
        acc.x += __shfl_xor_sync(0xffffffffu, acc.x, m);
        acc.y += __shfl_xor_sync(0xffffffffu, acc.y, m);
        acc.z += __shfl_xor_sync(0xffffffffu, acc.z, m);
        acc.w += __shfl_xor_sync(0xffffffffu, acc.w, m);
    }
    // lanes 0 (j 0-3) and 1 (j 4-6) hold the sums; lanes 0-6 write out[n*7+j]
    if (lane < F_OUT) {
        int srcl = lane >> 2;      // 0 or 1
        int comp = lane & 3;
        float cx = __shfl_sync(0x7fu, acc.x, srcl);
        float cy = __shfl_sync(0x7fu, acc.y, srcl);
        float cz = __shfl_sync(0x7fu, acc.z, srcl);
        float cw = __shfl_sync(0x7fu, acc.w, srcl);
        float v = (comp == 0) ? cx : (comp == 1) ? cy : (comp == 2) ? cz : cw;
        out[(size_t)gw * F_OUT + lane] = fmaf(v, g_nd[gw], b2[lane]);
    }
}

// ---------------- launch ------------------------------------------------------
extern "C" void kernel_launch(void* const* d_in, const int* in_sizes, int n_in,
                              void* d_out, int out_size) {
    const float* X   = (const float*)d_in[0];
    const int*   src = (const int*)  d_in[1];
    const int*   dst = (const int*)  d_in[2];
    const float* W1  = (const float*)d_in[3];
    const float* b1  = (const float*)d_in[4];
    const float* W2  = (const float*)d_in[5];
    const float* b2  = (const float*)d_in[6];
    float* out = (float*)d_out;

    const int g1_smem = 8 * KPAD * 8;   // 98304 bytes
    static int attr_done = 0;
    if (!attr_done) {   // idempotent host-side attribute, not a capture op
        cudaFuncSetAttribute(gemm1_kernel,
                             cudaFuncAttributeMaxDynamicSharedMemorySize, g1_smem);
        attr_done = 1;
    }

    zero_kernel       <<<(N_NODES + 255) / 256, 256>>>();
    degree_kernel     <<<N_EDGES / 4 / 256, 256>>>(src, dst);
    norm_offset_kernel<<<(N_NODES + 255) / 256, 256>>>();
    place_kernel      <<<N_EDGES / 4 / 256, 256>>>(src, dst);
    gemm1_kernel      <<<G1_GRID, 256, g1_smem>>>(X, W1);
    agg1_kernel       <<<N_NODES / 8, 256>>>();
    gemm2_kernel      <<<(N_NODES + 255) / 256, 256>>>(b1, W2);
    agg2_final_kernel <<<N_NODES / 8, 256>>>(b2, out);
}

// round 10
// speedup vs baseline: 1.0756x; 1.0756x over previous
#include <cuda_runtime.h>
#include <cstdint>

#define N_NODES 100000
#define N_EDGES 3200000
#define F_IN    1433
#define F_HID   16
#define F_OUT   7

#define KPAD     1536            // F_IN padded to multiple of 128 (zero-filled W)
#define G1_GRID  296             // 148 SMs x 2 blocks
#define NCHUNK   (N_NODES / 4)   // 25000 4-row warp chunks

// ---------------- scratch (device globals; no allocation allowed) ----------
__device__ float g_h1  [N_NODES * F_HID];   // X @ W1 (unscaled, then *= ns)
__device__ float g_agg1[N_NODES * F_HID];   // gather-aggregated layer 1
__device__ float g_h2  [N_NODES * 8];       // padded to 8
__device__ float g_degout[N_NODES];
__device__ int   g_degin [N_NODES];         // int in-degree (CSR)
__device__ float g_ns[N_NODES];
__device__ float g_nd[N_NODES];
__device__ int   g_off   [N_NODES];         // CSR range start per dst
__device__ int   g_cursor[N_NODES];         // initialized to g_off
__device__ int   g_csr_src[N_EDGES];
__device__ int   g_total;

// ---- packed f32x2 helpers (sm_103a FFMA2 — PTX-only form) ------------------
__device__ __forceinline__ unsigned long long fma2(unsigned long long a,
                                                   unsigned long long b,
                                                   unsigned long long c) {
    unsigned long long d;
    asm("fma.rn.f32x2 %0, %1, %2, %3;" : "=l"(d) : "l"(a), "l"(b), "l"(c));
    return d;
}
__device__ __forceinline__ unsigned long long add2(unsigned long long a,
                                                   unsigned long long b) {
    unsigned long long d;
    asm("add.rn.f32x2 %0, %1, %2;" : "=l"(d) : "l"(a), "l"(b));
    return d;
}
__device__ __forceinline__ unsigned long long splat2(float x) {
    unsigned long long d;
    asm("mov.b64 %0, {%1, %1};" : "=l"(d) : "f"(x));
    return d;
}
__device__ __forceinline__ float2 unpack2(unsigned long long v) {
    float2 r;
    asm("mov.b64 {%0, %1}, %2;" : "=f"(r.x), "=f"(r.y) : "l"(v));
    return r;
}
__device__ __forceinline__ float ldcs(const float* p) {
    float v;
    asm("ld.global.cs.f32 %0, [%1];" : "=f"(v) : "l"(p));
    return v;
}

// ---------------- zeroing (graph-replay safe) --------------------------------
__global__ void zero_kernel() {
    int t = blockIdx.x * blockDim.x + threadIdx.x;
    if (t < N_NODES) { g_degout[t] = 0.f; g_degin[t] = 0; }
    if (t == 0) g_total = 0;
}

// ---------------- degrees (4 edges/thread) ------------------------------------
__global__ void degree_kernel(const int* __restrict__ src,
                              const int* __restrict__ dst) {
    int base = (blockIdx.x * blockDim.x + threadIdx.x) * 4;
    if (base >= N_EDGES) return;
    int4 s4 = *(const int4*)(src + base);
    int4 d4 = *(const int4*)(dst + base);
    atomicAdd(&g_degout[s4.x], 1.0f);
    atomicAdd(&g_degout[s4.y], 1.0f);
    atomicAdd(&g_degout[s4.z], 1.0f);
    atomicAdd(&g_degout[s4.w], 1.0f);
    atomicAdd(&g_degin[d4.x], 1);
    atomicAdd(&g_degin[d4.y], 1);
    atomicAdd(&g_degin[d4.z], 1);
    atomicAdd(&g_degin[d4.w], 1);
}

// ---------------- norms + CSR offsets (warp-aggregated range assignment) ----
__global__ void norm_offset_kernel() {
    int n = blockIdx.x * blockDim.x + threadIdx.x;
    if (n >= N_NODES) return;
    int lane = threadIdx.x & 31;
    int d = g_degin[n];

    int incl = d;
#pragma unroll
    for (int o = 1; o < 32; o <<= 1) {
        int v = __shfl_up_sync(0xffffffffu, incl, o);
        if (lane >= o) incl += v;
    }
    int base = 0;
    if (lane == 31) base = atomicAdd(&g_total, incl);
    base = __shfl_sync(0xffffffffu, base, 31);

    int off = base + incl - d;
    g_off[n]    = off;
    g_cursor[n] = off;
    g_ns[n] = rsqrtf(fmaxf(g_degout[n], 1.0f));
    g_nd[n] = rsqrtf(fmaxf((float)d, 1.0f));
}

// ---------------- CSR edge placement (4 edges/thread) -------------------------
__global__ void place_kernel(const int* __restrict__ src,
                             const int* __restrict__ dst) {
    int base = (blockIdx.x * blockDim.x + threadIdx.x) * 4;
    if (base >= N_EDGES) return;
    int4 d4 = *(const int4*)(dst + base);
    int4 s4 = *(const int4*)(src + base);
    int p0 = atomicAdd(&g_cursor[d4.x], 1);
    int p1 = atomicAdd(&g_cursor[d4.y], 1);
    int p2 = atomicAdd(&g_cursor[d4.z], 1);
    int p3 = atomicAdd(&g_cursor[d4.w], 1);
    g_csr_src[p0] = s4.x;
    g_csr_src[p1] = s4.y;
    g_csr_src[p2] = s4.z;
    g_csr_src[p3] = s4.w;
}

// ---------------- GEMM1: h1 = X @ W1 (UNSCALED; ns applied after join) -------
__global__ __launch_bounds__(256, 2) void gemm1_kernel(const float* __restrict__ X,
                                                       const float* __restrict__ W) {
    extern __shared__ unsigned long long sWp[];   // [8][KPAD] packed float2

    const float2* Wv = (const float2*)W;          // Wv[k*8 + p]
    for (int idx = threadIdx.x; idx < 8 * KPAD; idx += 256) {
        int k = idx >> 3, p = idx & 7;
        float2 v = (k < F_IN) ? Wv[k * 8 + p] : make_float2(0.f, 0.f);
        unsigned long long pk;
        asm("mov.b64 %0, {%1, %2};" : "=l"(pk) : "f"(v.x), "f"(v.y));
        sWp[p * KPAD + k] = pk;
    }
    __syncthreads();

    const int lane = threadIdx.x & 31;
    const int gw   = blockIdx.x * 8 + (threadIdx.x >> 5);

    for (int chunk = gw; chunk < NCHUNK; chunk += G1_GRID * 8) {
        const unsigned m0   = (unsigned)chunk * 4u;
        const unsigned base = m0 * (unsigned)F_IN;

        unsigned long long acc[32];
#pragma unroll
        for (int a = 0; a < 32; a++) acc[a] = 0ull;

        float Axa[4], Axb[4];
        float Bxa[4], Bxb[4];
        float Cxa[4], Cxb[4];

#define COMPUTE_BLOCK(k0v, xa, xb)                                            \
        {                                                                     \
            const int kA = (k0v) + lane;                                      \
            unsigned long long xx[4];                                         \
            _Pragma("unroll")                                                 \
            for (int i = 0; i < 4; i++) xx[i] = splat2(xa[i]);                \
            _Pragma("unroll")                                                 \
            for (int p = 0; p < 8; p++) {                                     \
                unsigned long long w = sWp[p * KPAD + kA];                    \
                _Pragma("unroll")                                             \
                for (int i = 0; i < 4; i++)                                   \
                    acc[i * 8 + p] = fma2(xx[i], w, acc[i * 8 + p]);          \
            }                                                                 \
            const int kB = (k0v) + 32 + lane;                                 \
            _Pragma("unroll")                                                 \
            for (int i = 0; i < 4; i++) xx[i] = splat2(xb[i]);                \
            _Pragma("unroll")                                                 \
            for (int p = 0; p < 8; p++) {                                     \
                unsigned long long w = sWp[p * KPAD + kB];                    \
                _Pragma("unroll")                                             \
                for (int i = 0; i < 4; i++)                                   \
                    acc[i * 8 + p] = fma2(xx[i], w, acc[i * 8 + p]);          \
            }                                                                 \
        }

#define PREFETCH_BLOCK(k0v, xa, xb)                                           \
        {                                                                     \
            const unsigned ka = (unsigned)min((k0v) + lane,      F_IN - 1);   \
            const unsigned kb = (unsigned)min((k0v) + 32 + lane, F_IN - 1);   \
            _Pragma("unroll")                                                 \
            for (int i = 0; i < 4; i++) {                                     \
                xa[i] = ldcs(X + base + (unsigned)i * F_IN + ka);             \
                xb[i] = ldcs(X + base + (unsigned)i * F_IN + kb);             \
            }                                                                 \
        }

        PREFETCH_BLOCK(0,  Axa, Axb);
        PREFETCH_BLOCK(64, Bxa, Bxb);

#pragma unroll 1
        for (int t = 0; t < 8; t++) {
            const int kb0 = t * 192;
            PREFETCH_BLOCK(kb0 + 128, Cxa, Cxb);
            COMPUTE_BLOCK (kb0,       Axa, Axb);
            PREFETCH_BLOCK(kb0 + 192, Axa, Axb);
            COMPUTE_BLOCK (kb0 + 64,  Bxa, Bxb);
            PREFETCH_BLOCK(kb0 + 256, Bxa, Bxb);
            COMPUTE_BLOCK (kb0 + 128, Cxa, Cxb);
        }
#undef COMPUTE_BLOCK
#undef PREFETCH_BLOCK

        // transpose-reduce: lane l ends with acc slot (row = l>>3, pcol = l&7)
        {
            int n = 32;
#pragma unroll
            for (int m = 16; m > 0; m >>= 1) {
                n >>= 1;
#pragma unroll
                for (int j = 0; j < 16; j++) {
                    if (j >= n) break;
                    unsigned long long mine = (lane & m) ? acc[j]     : acc[j + n];
                    unsigned long long keep = (lane & m) ? acc[j + n] : acc[j];
                    unsigned long long recv = __shfl_xor_sync(0xffffffffu, mine, m);
                    acc[j] = add2(keep, recv);
                }
            }
        }
        {
            const int i = lane >> 3, p = lane & 7;
            float2 v = unpack2(acc[0]);
            float2* o = (float2*)(g_h1 + (size_t)(m0 + i) * F_HID);
            o[p] = v;   // unscaled
        }
    }
}

// ---------------- scale h1 by ns (after fork join) ---------------------------
__global__ void scale_h1_kernel() {
    int t = blockIdx.x * blockDim.x + threadIdx.x;   // one float4 each
    if (t >= N_NODES * 4) return;
    float s = g_ns[t >> 2];
    float4 v = ((const float4*)g_h1)[t];
    v.x *= s; v.y *= s; v.z *= s; v.w *= s;
    ((float4*)g_h1)[t] = v;
}

// ---------------- agg1: agg1[n] = sum_{e in CSR[n]} h1[src(e)]  (16 wide) ---
__global__ __launch_bounds__(256) void agg1_kernel() {
    int gw   = blockIdx.x * 8 + (threadIdx.x >> 5);   // node id (grid exact)
    int lane = threadIdx.x & 31;
    int q  = lane & 3;
    int es = lane >> 2;

    int o  = g_off[gw];
    int nE = g_degin[gw];

    float4 acc = make_float4(0.f, 0.f, 0.f, 0.f);
    const float4* h1v = (const float4*)g_h1;
    for (int i = es; i < nE; i += 8) {
        int s = __ldg(&g_csr_src[o + i]);
        float4 v = h1v[(size_t)s * 4 + q];
        acc.x += v.x; acc.y += v.y; acc.z += v.z; acc.w += v.w;
    }
#pragma unroll
    for (int m = 4; m <= 16; m <<= 1) {
        acc.x += __shfl_xor_sync(0xffffffffu, acc.x, m);
        acc.y += __shfl_xor_sync(0xffffffffu, acc.y, m);
        acc.z += __shfl_xor_sync(0xffffffffu, acc.z, m);
        acc.w += __shfl_xor_sync(0xffffffffu, acc.w, m);
    }
    if (lane < 4) ((float4*)g_agg1)[(size_t)gw * 4 + lane] = acc;
}

// ---------------- GEMM2: h2 = diag(ns) * relu(agg1*nd + b1) @ W2 ------------
__global__ void gemm2_kernel(const float* __restrict__ b1,
                             const float* __restrict__ W2) {
    __shared__ float sW[F_HID * F_OUT];
    __shared__ float sb[F_HID];
    if (threadIdx.x < F_HID * F_OUT) sW[threadIdx.x] = W2[threadIdx.x];
    if (threadIdx.x < F_HID)         sb[threadIdx.x] = b1[threadIdx.x];
    __syncthreads();

    int n = blockIdx.x * blockDim.x + threadIdx.x;
    if (n >= N_NODES) return;

    float ndv = g_nd[n], nsv = g_ns[n];
    const float4* a4 = (const float4*)(g_agg1 + (size_t)n * F_HID);
    float x[F_HID];
#pragma unroll
    for (int q = 0; q < 4; q++) {
        float4 v = a4[q];
        x[q*4+0] = v.x; x[q*4+1] = v.y; x[q*4+2] = v.z; x[q*4+3] = v.w;
    }
    float o[F_OUT];
#pragma unroll
    for (int j = 0; j < F_OUT; j++) o[j] = 0.f;
#pragma unroll
    for (int i = 0; i < F_HID; i++) {
        float xi = fmaxf(fmaf(x[i], ndv, sb[i]), 0.f) * nsv;
#pragma unroll
        for (int j = 0; j < F_OUT; j++) o[j] = fmaf(xi, sW[i * F_OUT + j], o[j]);
    }
    float4* hp = (float4*)(g_h2 + (size_t)n * 8);
    hp[0] = make_float4(o[0], o[1], o[2], o[3]);
    hp[1] = make_float4(o[4], o[5], o[6], 0.f);   // pad lane stays 0
}

// ---------------- agg2 + finalize: out[n] = (sum h2[src]) * nd + b2 ----------
__global__ __launch_bounds__(256) void agg2_final_kernel(const float* __restrict__ b2,
                                                         float* __restrict__ out) {
    int gw   = blockIdx.x * 8 + (threadIdx.x >> 5);
    int lane = threadIdx.x & 31;
    int q  = lane & 1;
    int es = lane >> 1;

    int o  = g_off[gw];
    int nE = g_degin[gw];

    float4 acc = make_float4(0.f, 0.f, 0.f, 0.f);
    const float4* h2v = (const float4*)g_h2;
    for (int i = es; i < nE; i += 16) {
        int s = __ldg(&g_csr_src[o + i]);
        float4 v = h2v[(size_t)s * 2 + q];
        acc.x += v.x; acc.y += v.y; acc.z += v.z; acc.w += v.w;
    }
#pragma unroll
    for (int m = 2; m <= 16; m <<= 1) {
        acc.x += __shfl_xor_sync(0xffffffffu, acc.x, m);
        acc.y += __shfl_xor_sync(0xffffffffu, acc.y, m);
        acc.z += __shfl_xor_sync(0xffffffffu, acc.z, m);
        acc.w += __shfl_xor_sync(0xffffffffu, acc.w, m);
    }
    if (lane < F_OUT) {
        int srcl = lane >> 2;      // 0 or 1
        int comp = lane & 3;
        float cx = __shfl_sync(0x7fu, acc.x, srcl);
        float cy = __shfl_sync(0x7fu, acc.y, srcl);
        float cz = __shfl_sync(0x7fu, acc.z, srcl);
        float cw = __shfl_sync(0x7fu, acc.w, srcl);
        float v = (comp == 0) ? cx : (comp == 1) ? cy : (comp == 2) ? cz : cw;
        out[(size_t)gw * F_OUT + lane] = fmaf(v, g_nd[gw], b2[lane]);
    }
}

// ---------------- launch ------------------------------------------------------
extern "C" void kernel_launch(void* const* d_in, const int* in_sizes, int n_in,
                              void* d_out, int out_size) {
    const float* X   = (const float*)d_in[0];
    const int*   src = (const int*)  d_in[1];
    const int*   dst = (const int*)  d_in[2];
    const float* W1  = (const float*)d_in[3];
    const float* b1  = (const float*)d_in[4];
    const float* W2  = (const float*)d_in[5];
    const float* b2  = (const float*)d_in[6];
    float* out = (float*)d_out;

    const int g1_smem = 8 * KPAD * 8;   // 98304 bytes

    static int initialized = 0;
    static cudaStream_t s2;
    static cudaEvent_t evFork, evJoin;
    if (!initialized) {   // host-side one-time setup (no device memory)
        cudaFuncSetAttribute(gemm1_kernel,
                             cudaFuncAttributeMaxDynamicSharedMemorySize, g1_smem);
        cudaStreamCreateWithFlags(&s2, cudaStreamNonBlocking);
        cudaEventCreateWithFlags(&evFork, cudaEventDisableTiming);
        cudaEventCreateWithFlags(&evJoin, cudaEventDisableTiming);
        initialized = 1;
    }

    // ---- fork: CSR build on s2 concurrent with gemm1 on the main stream ----
    cudaEventRecord(evFork, 0);
    cudaStreamWaitEvent(s2, evFork, 0);

    zero_kernel       <<<(N_NODES + 255) / 256, 256, 0, s2>>>();
    degree_kernel     <<<N_EDGES / 4 / 256, 256, 0, s2>>>(src, dst);
    norm_offset_kernel<<<(N_NODES + 255) / 256, 256, 0, s2>>>();
    place_kernel      <<<N_EDGES / 4 / 256, 256, 0, s2>>>(src, dst);

    gemm1_kernel      <<<G1_GRID, 256, g1_smem>>>(X, W1);   // main stream

    // ---- join: everything below needs both gemm1 and the CSR/norms ---------
    cudaEventRecord(evJoin, s2);
    cudaStreamWaitEvent(0, evJoin, 0);

    scale_h1_kernel   <<<(N_NODES * 4 + 255) / 256, 256>>>();
    agg1_kernel       <<<N_NODES / 8, 256>>>();
    gemm2_kernel      <<<(N_NODES + 255) / 256, 256>>>(b1, W2);
    agg2_final_kernel <<<N_NODES / 8, 256>>>(b2, out);
}